// round 17
// baseline (speedup 1.0000x reference)
#include <cuda_runtime.h>
#include <cstdint>

// Problem (fixed by reference):
//   x  : (2048, 16384) fp32   (B, Q*S)
//   W1 : (128, 128, 32) fp32  (Q, S, H)
//   b1 : (128, 32),  W2 : (128, 32, 1),  b2 : (128, 1)
//   out: (2048, 128) fp32     (B, Q)
#define Q_   128
#define S_   128
#define H_   32
#define C_   (Q_ * S_)
#define NB   512            // batches per block
#define SCH  8              // s rows per pipeline stage
#define NCH  (S_ / SCH)     // 16 stages
#define XPAD 516            // xs row stride (floats); 16B-aligned strides
#define THREADS 256

// packed fp32x2 FMA (Blackwell FFMA2): two independent IEEE fp32 FMAs
__device__ __forceinline__ void fma_f32x2(unsigned long long& d,
                                          unsigned long long a,
                                          unsigned long long b,
                                          unsigned long long c) {
    asm("fma.rn.f32x2 %0, %1, %2, %3;" : "=l"(d) : "l"(a), "l"(b), "l"(c));
}
__device__ __forceinline__ unsigned long long pack2(float lo, float hi) {
    unsigned long long r;
    asm("mov.b64 %0, {%1, %2};" : "=l"(r) : "f"(lo), "f"(hi));
    return r;
}
__device__ __forceinline__ void unpack2(float& lo, float& hi, unsigned long long v) {
    asm("mov.b64 {%0, %1}, %2;" : "=f"(lo), "=f"(hi) : "l"(v));
}

__global__ __launch_bounds__(THREADS, 2)
void divenc_kernel(const float* __restrict__ x,
                   const float* __restrict__ W1,
                   const float* __restrict__ b1,
                   const float* __restrict__ W2,
                   const float* __restrict__ b2,
                   float* __restrict__ out)
{
    extern __shared__ float smem[];
    float* w1s = smem;                  // 4096 floats (16 KB)
    float* xs0 = smem + S_ * H_;        // 2 buffers of SCH*XPAD floats (~33 KB)

    const int q   = blockIdx.y;
    const int b0  = blockIdx.x * NB;
    const int tid = threadIdx.x;
    const int warp = tid >> 5;
    const int lane = tid & 31;
    const int hg = warp >> 2;                    // 0..1 -> h = hg*16 + (0..15)
    const int bt = ((warp & 3) << 5) | lane;     // 0..127 -> b = bt*4 + (0..3)

    // ---- stage W1[q] (128x32) into smem, coalesced float4 ----
    {
        const float4* src = (const float4*)(W1 + (size_t)q * (S_ * H_));
        float4* dst = (float4*)w1s;
        #pragma unroll
        for (int i = tid; i < (S_ * H_) / 4; i += THREADS)
            dst[i] = src[i];
    }

    // 4 batches x 8 h-pairs of packed-f32x2 accumulators (64 fp32 accs)
    unsigned long long acc2[4][8];
    #pragma unroll
    for (int i = 0; i < 4; ++i)
        #pragma unroll
        for (int jp = 0; jp < 8; ++jp) acc2[i][jp] = 0ULL;

    // each thread stages TWO batch rows: tid and tid+256
    const float4* xrow0 = (const float4*)(x + (size_t)(b0 + tid) * C_ + (size_t)q * S_);
    const float4* xrow1 = (const float4*)(x + (size_t)(b0 + tid + 256) * C_ + (size_t)q * S_);

    // ---- preload stage 0 (per row: SCH=8 floats = 2 float4) ----
    float4 A0 = xrow0[0], A1 = xrow0[1];
    float4 A2 = xrow1[0], A3 = xrow1[1];

    #pragma unroll 1
    for (int ch = 0; ch < NCH; ++ch) {
        float* buf = xs0 + (ch & 1) * (SCH * XPAD);

        // ---- STS transpose: buf[s][b], conflict-free (lanes -> consecutive b) ----
        buf[0 * XPAD + tid] = A0.x; buf[1 * XPAD + tid] = A0.y;
        buf[2 * XPAD + tid] = A0.z; buf[3 * XPAD + tid] = A0.w;
        buf[4 * XPAD + tid] = A1.x; buf[5 * XPAD + tid] = A1.y;
        buf[6 * XPAD + tid] = A1.z; buf[7 * XPAD + tid] = A1.w;
        buf[0 * XPAD + tid + 256] = A2.x; buf[1 * XPAD + tid + 256] = A2.y;
        buf[2 * XPAD + tid + 256] = A2.z; buf[3 * XPAD + tid + 256] = A2.w;
        buf[4 * XPAD + tid + 256] = A3.x; buf[5 * XPAD + tid + 256] = A3.y;
        buf[6 * XPAD + tid + 256] = A3.z; buf[7 * XPAD + tid + 256] = A3.w;

        // ---- prefetch next stage (overlaps with this stage's compute) ----
        if (ch + 1 < NCH) {
            A0 = xrow0[(ch + 1) * 2];  A1 = xrow0[(ch + 1) * 2 + 1];
            A2 = xrow1[(ch + 1) * 2];  A3 = xrow1[(ch + 1) * 2 + 1];
        }

        __syncthreads();   // buf visible; also orders buffer reuse (2-stage distance)

        // ---- compute SCH s-steps: per s = 1 LDS.128 (x, 4 batches)
        //      + 4 LDS.128 (W pairs, broadcast) + 4 bcast packs + 32 fma.rn.f32x2 ----
        const float* wbase = w1s + (ch * SCH) * H_ + hg * 16;
        #pragma unroll
        for (int s = 0; s < SCH; ++s) {
            float4 xv = *(const float4*)(buf + s * XPAD + bt * 4);   // 4 batches
            ulonglong2 wa = *(const ulonglong2*)(wbase + s * H_);      // h pairs 0,1
            ulonglong2 wb = *(const ulonglong2*)(wbase + s * H_ + 4);  // h pairs 2,3
            ulonglong2 wc = *(const ulonglong2*)(wbase + s * H_ + 8);  // h pairs 4,5
            ulonglong2 wd = *(const ulonglong2*)(wbase + s * H_ + 12); // h pairs 6,7
            unsigned long long w2p[8] = {wa.x, wa.y, wb.x, wb.y,
                                         wc.x, wc.y, wd.x, wd.y};
            float xr[4] = {xv.x, xv.y, xv.z, xv.w};
            #pragma unroll
            for (int i = 0; i < 4; ++i) {
                unsigned long long x2 = pack2(xr[i], xr[i]);           // broadcast pack
                #pragma unroll
                for (int jp = 0; jp < 8; ++jp)
                    fma_f32x2(acc2[i][jp], x2, w2p[jp], acc2[i][jp]);
            }
        }
    }

    // ---- epilogue: + b1, ELU(alpha=1), dot with W2 over this thread's 16 h ----
    float part[4];
    {
        const float* b1q = b1 + q * H_ + hg * 16;
        const float* w2q = W2 + q * H_ + hg * 16;
        float b1v[16], w2v[16];
        #pragma unroll
        for (int j = 0; j < 16; ++j) { b1v[j] = b1q[j]; w2v[j] = w2q[j]; }
        #pragma unroll
        for (int i = 0; i < 4; ++i) {
            float sum = 0.0f;
            #pragma unroll
            for (int jp = 0; jp < 8; ++jp) {
                float lo, hi;
                unpack2(lo, hi, acc2[i][jp]);
                float z0 = lo + b1v[2 * jp];
                float z1 = hi + b1v[2 * jp + 1];
                float e0 = (z0 > 0.0f) ? z0 : expm1f(z0);
                float e1 = (z1 > 0.0f) ? z1 : expm1f(z1);
                sum = fmaf(e0, w2v[2 * jp], sum);
                sum = fmaf(e1, w2v[2 * jp + 1], sum);
            }
            part[i] = sum;
        }
    }

    // ---- cross-warp reduction over the 2 h-groups ----
    __syncthreads();   // all compute done before reusing xs
    float* red = xs0;  // needs 2*NB = 1024 floats
    #pragma unroll
    for (int i = 0; i < 4; ++i)
        red[hg * NB + bt * 4 + i] = part[i];
    __syncthreads();

    const float bias2 = b2[q];
    float r0 = red[tid] + red[NB + tid] + bias2;
    float r1 = red[tid + 256] + red[NB + tid + 256] + bias2;
    out[(size_t)(b0 + tid) * Q_ + q] = r0;
    out[(size_t)(b0 + tid + 256) * Q_ + q] = r1;
}

extern "C" void kernel_launch(void* const* d_in, const int* in_sizes, int n_in,
                              void* d_out, int out_size)
{
    const float* x  = (const float*)d_in[0];
    const float* W1 = (const float*)d_in[1];
    const float* b1 = (const float*)d_in[2];
    const float* W2 = (const float*)d_in[3];
    const float* b2 = (const float*)d_in[4];
    float* out = (float*)d_out;

    const int B = in_sizes[0] / C_;   // 2048
    const size_t smem_bytes = (size_t)(S_ * H_ + 2 * SCH * XPAD) * sizeof(float); // 49,408 B

    cudaFuncSetAttribute(divenc_kernel,
                         cudaFuncAttributeMaxDynamicSharedMemorySize,
                         (int)smem_bytes);

    dim3 grid(B / NB, Q_);   // (4, 128)
    divenc_kernel<<<grid, THREADS, smem_bytes>>>(x, W1, b1, W2, b2, out);
}